// round 15
// baseline (speedup 1.0000x reference)
#include <cuda_runtime.h>
#include <cuda_bf16.h>
#include <math.h>
#include <stdint.h>

// Problem shapes (fixed by the dataset)
#define Bb 4
#define Tt 16
#define Ss 256
#define Dd 512
#define Nn 8
#define Mm (Bb * Ss)   // 1024 GEMM rows
#define Kk Dd          // 512  GEMM K
#define Nc (Dd * Nn)   // 4096 GEMM cols

// ---------------------------------------------------------------------------
// Device scratch (no dynamic allocation allowed)
// ---------------------------------------------------------------------------
__device__ __align__(16) __nv_bfloat16 g_Ehi[(size_t)Mm * Kk];       // [m][k]
__device__ __align__(16) __nv_bfloat16 g_Elo[(size_t)Mm * Kk];
__device__ __align__(16) __nv_bfloat16 g_Whi[(size_t)Kk * Nc];       // [k][n]
__device__ __align__(16) __nv_bfloat16 g_Wlo[(size_t)Kk * Nc];

// ---------------------------------------------------------------------------
// Conversion: fp32 -> bf16 hi/lo split. 8 elems per thread, 16B stores.
// ---------------------------------------------------------------------------
#define E_F4 ((Mm * Kk) / 4)      // 131072
#define W_F4 ((Kk * Nc) / 4)      // 524288
#define CONV_THREADS ((E_F4 + W_F4) / 2)

__device__ __forceinline__ uint32_t pack_hi2(float a, float b) {
    uint32_t ha = (uint32_t)__bfloat16_as_ushort(__float2bfloat16(a));
    uint32_t hb = (uint32_t)__bfloat16_as_ushort(__float2bfloat16(b));
    return ha | (hb << 16);
}
__device__ __forceinline__ uint32_t pack_lo2(float a, float b) {
    float fa = __bfloat162float(__float2bfloat16(a));
    float fb = __bfloat162float(__float2bfloat16(b));
    uint32_t la = (uint32_t)__bfloat16_as_ushort(__float2bfloat16(a - fa));
    uint32_t lb = (uint32_t)__bfloat16_as_ushort(__float2bfloat16(b - fb));
    return la | (lb << 16);
}
__device__ __forceinline__ void conv8(const float4* __restrict__ src,
                                      uint4* __restrict__ dhi,
                                      uint4* __restrict__ dlo) {
    const float4 v0 = __ldcs(src);
    const float4 v1 = __ldcs(src + 1);
    uint4 h, l;
    h.x = pack_hi2(v0.x, v0.y); h.y = pack_hi2(v0.z, v0.w);
    h.z = pack_hi2(v1.x, v1.y); h.w = pack_hi2(v1.z, v1.w);
    l.x = pack_lo2(v0.x, v0.y); l.y = pack_lo2(v0.z, v0.w);
    l.z = pack_lo2(v1.x, v1.y); l.w = pack_lo2(v1.z, v1.w);
    __stcs(dhi, h);
    __stcs(dlo, l);
}

__global__ __launch_bounds__(256) void conv_kernel(const float* __restrict__ E,
                                                   const float* __restrict__ W) {
    const int t = blockIdx.x * 256 + threadIdx.x;
    const int i = t * 2;
    if (i < E_F4) {
        conv8((const float4*)E + i, (uint4*)g_Ehi + t, (uint4*)g_Elo + t);
    } else {
        const int j = i - E_F4;
        const int tj = t - E_F4 / 2;
        conv8((const float4*)W + j, (uint4*)g_Whi + tj, (uint4*)g_Wlo + tj);
    }
}

// ---------------------------------------------------------------------------
// Fused GEMM (3-term Markidis split) + tile-local encode.
// CTA tile 64x128, 128 threads, BK=32, 2-stage cp.async, 4 CTAs/SM,
// grid 512 (single wave). After the mainloop, sigmoid(acc+bias) is staged
// in SMEM (overlaying dead stage buffers), then this CTA encodes its own
// 64 rows x 16 d-groups directly -> no global pop_rates array at all.
// ---------------------------------------------------------------------------
#define BM 64
#define BN 128
#define BK 32
#define NK (Kk / BK)          // 16

#define A_PITCH 40            // bf16 elems per A row (32+8 pad) -> 80 B
#define B_PITCH 136           // bf16 elems per B row (128+8 pad) -> 272 B
#define A_BYTES (BM * A_PITCH * 2)   // 5120
#define B_BYTES (BK * B_PITCH * 2)   // 8704
#define ST_AH 0
#define ST_AL A_BYTES
#define ST_BH (2 * A_BYTES)
#define ST_BL (2 * A_BYTES + B_BYTES)
#define STAGE_BYTES (2 * A_BYTES + 2 * B_BYTES)   // 27648
#define FUSED_SMEM (2 * STAGE_BYTES)              // 55296

#define RP 132                // rates smem pitch in floats (64*132*4 = 33792 B)

__device__ __forceinline__ uint32_t smem_u32(const void* p) {
    uint32_t a;
    asm("{ .reg .u64 t; cvta.to.shared.u64 t, %1; cvt.u32.u64 %0, t; }"
        : "=r"(a) : "l"(p));
    return a;
}
__device__ __forceinline__ void cp16(uint32_t dst, const void* src) {
    asm volatile("cp.async.cg.shared.global [%0], [%1], 16;"
                 :: "r"(dst), "l"(src) : "memory");
}
__device__ __forceinline__ void ldsm_x4(uint32_t* r, uint32_t addr) {
    asm volatile("ldmatrix.sync.aligned.m8n8.x4.shared.b16 {%0,%1,%2,%3}, [%4];"
                 : "=r"(r[0]), "=r"(r[1]), "=r"(r[2]), "=r"(r[3]) : "r"(addr));
}
__device__ __forceinline__ void ldsm_x4t(uint32_t* r, uint32_t addr) {
    asm volatile("ldmatrix.sync.aligned.m8n8.x4.trans.shared.b16 {%0,%1,%2,%3}, [%4];"
                 : "=r"(r[0]), "=r"(r[1]), "=r"(r[2]), "=r"(r[3]) : "r"(addr));
}
__device__ __forceinline__ void mma16816(float* d, const uint32_t* a, const uint32_t* b) {
    asm volatile(
        "mma.sync.aligned.m16n8k16.row.col.f32.bf16.bf16.f32 "
        "{%0,%1,%2,%3}, {%4,%5,%6,%7}, {%8,%9}, {%0,%1,%2,%3};"
        : "+f"(d[0]), "+f"(d[1]), "+f"(d[2]), "+f"(d[3])
        : "r"(a[0]), "r"(a[1]), "r"(a[2]), "r"(a[3]), "r"(b[0]), "r"(b[1]));
}

// Accurate fp32 sin (Cody-Waite + degree-9 minimax); fast-math immune.
__device__ __forceinline__ float my_sinf(float x) {
    const float INV_PI = 0.318309886183790672f;
    const float PI_HI = 3.14159274101257324f;
    const float PI_LO = -8.74227765734758577e-08f;
    float kf = rintf(x * INV_PI);
    float r = fmaf(-kf, PI_HI, x);
    r = fmaf(-kf, PI_LO, r);
    float s = r * r;
    float p = fmaf(s, 2.6083159809786593e-06f, -1.9810690719168633e-04f);
    p = fmaf(s, p, 8.3330785855650902e-03f);
    p = fmaf(s, p, -1.6666659712791443e-01f);
    float res = fmaf(r * s, p, r);
    int k = (int)kf;
    return (k & 1) ? -res : res;
}

__global__ __launch_bounds__(128, 4) void fused_kernel(
    const float* __restrict__ bias,
    const float* __restrict__ emb, const float* __restrict__ noise,
    const float* __restrict__ freq_bands, const float* __restrict__ enc_w,
    const float* __restrict__ rate_rand, const float* __restrict__ pop_rand,
    float* __restrict__ out)
{
    extern __shared__ char smem[];
    const uint32_t sbase = smem_u32(smem);
    const int tid = threadIdx.x;
    const int wid = tid >> 5;
    const int ln = tid & 31;
    const int warp_m = wid & 1;       // 2 warps along M (32 rows each)
    const int warp_n = wid >> 1;      // 2 warps along N (64 cols each)
    const int bm = blockIdx.y * BM;
    const int bn = blockIdx.x * BN;

    // ---------------- GEMM mainloop (R8-proven config) ----------------
    // A: 256 16B-chunks per array -> 2 per thread (rows tid>>2 and +32)
    const int a_row0 = tid >> 2, a_seg = tid & 3;
    const int a_row1 = a_row0 + 32;
    // B: 512 chunks per array -> 4 per thread (rows tid>>4, +8, +16, +24)
    const int b_row0 = tid >> 4, b_seg = tid & 15;

    auto load_stage = [&](int it, int p) {
        const int k0 = it * BK;
        const uint32_t st = sbase + p * STAGE_BYTES;
        {
            const size_t g0 = (size_t)(bm + a_row0) * Kk + k0 + a_seg * 8;
            const size_t g1 = (size_t)(bm + a_row1) * Kk + k0 + a_seg * 8;
            const uint32_t s0 = st + ST_AH + a_row0 * (A_PITCH * 2) + a_seg * 16;
            const uint32_t s1 = st + ST_AH + a_row1 * (A_PITCH * 2) + a_seg * 16;
            cp16(s0, g_Ehi + g0);
            cp16(s1, g_Ehi + g1);
            cp16(s0 + (ST_AL - ST_AH), g_Elo + g0);
            cp16(s1 + (ST_AL - ST_AH), g_Elo + g1);
        }
#pragma unroll
        for (int r = 0; r < 4; r++) {
            const int brow = b_row0 + r * 8;
            const size_t g = (size_t)(k0 + brow) * Nc + bn + b_seg * 8;
            const uint32_t s = st + ST_BH + brow * (B_PITCH * 2) + b_seg * 16;
            cp16(s, g_Whi + g);
            cp16(s + (ST_BL - ST_BH), g_Wlo + g);
        }
        asm volatile("cp.async.commit_group;" ::: "memory");
    };

    float acc[2][8][4];
#pragma unroll
    for (int i = 0; i < 2; i++)
#pragma unroll
        for (int n = 0; n < 8; n++)
#pragma unroll
            for (int c = 0; c < 4; c++) acc[i][n][c] = 0.0f;

    const int lm_row = ln & 15;
    const int lm_half = ln >> 4;

    load_stage(0, 0);

    for (int it = 0; it < NK; it++) {
        const int p = it & 1;
        if (it + 1 < NK) load_stage(it + 1, p ^ 1);
        if (it + 1 < NK) { asm volatile("cp.async.wait_group 1;" ::: "memory"); }
        else             { asm volatile("cp.async.wait_group 0;" ::: "memory"); }
        __syncthreads();

        const uint32_t st = sbase + p * STAGE_BYTES;
        const uint32_t a_hi = st + ST_AH, a_lo = st + ST_AL;
        const uint32_t b_hi = st + ST_BH, b_lo = st + ST_BL;

#pragma unroll
        for (int j = 0; j < 2; j++) {
            uint32_t ah[2][4], al[2][4], bh[8][2], bl[8][2];
#pragma unroll
            for (int i = 0; i < 2; i++) {
                const uint32_t off =
                    (uint32_t)(warp_m * 32 + i * 16 + lm_row) * (A_PITCH * 2)
                    + (uint32_t)(j * 16 + lm_half * 8) * 2;
                ldsm_x4(ah[i], a_hi + off);
                ldsm_x4(al[i], a_lo + off);
            }
#pragma unroll
            for (int p4 = 0; p4 < 4; p4++) {
                const uint32_t off =
                    (uint32_t)(j * 16 + lm_row) * (B_PITCH * 2)
                    + (uint32_t)(warp_n * 64 + p4 * 16 + lm_half * 8) * 2;
                uint32_t r[4];
                ldsm_x4t(r, b_hi + off);
                bh[2 * p4][0] = r[0]; bh[2 * p4][1] = r[1];
                bh[2 * p4 + 1][0] = r[2]; bh[2 * p4 + 1][1] = r[3];
                ldsm_x4t(r, b_lo + off);
                bl[2 * p4][0] = r[0]; bl[2 * p4][1] = r[1];
                bl[2 * p4 + 1][0] = r[2]; bl[2 * p4 + 1][1] = r[3];
            }
#pragma unroll
            for (int i = 0; i < 2; i++)
#pragma unroll
                for (int n = 0; n < 8; n++) {
                    mma16816(acc[i][n], ah[i], bh[n]);
                    mma16816(acc[i][n], ah[i], bl[n]);
                    mma16816(acc[i][n], al[i], bh[n]);
                }
        }
        __syncthreads();
    }

    // -------- Epilogue: sigmoid(acc+bias) -> SMEM rates[64][RP] --------
    float* rates = (float*)smem;          // overlays dead stage buffers
    const int er = ln >> 2;
    const int ec = (ln & 3) * 2;
#pragma unroll
    for (int i = 0; i < 2; i++) {
        const int rl = warp_m * 32 + i * 16 + er;   // local row
#pragma unroll
        for (int n = 0; n < 8; n++) {
            const int cl = warp_n * 64 + n * 8 + ec;
            const float b0 = __ldg(bias + bn + cl);
            const float b1 = __ldg(bias + bn + cl + 1);
            rates[rl * RP + cl]           = 1.0f / (1.0f + expf(-(acc[i][n][0] + b0)));
            rates[rl * RP + cl + 1]       = 1.0f / (1.0f + expf(-(acc[i][n][1] + b1)));
            rates[(rl + 8) * RP + cl]     = 1.0f / (1.0f + expf(-(acc[i][n][2] + b0)));
            rates[(rl + 8) * RP + cl + 1] = 1.0f / (1.0f + expf(-(acc[i][n][3] + b1)));
        }
    }
    __syncthreads();

    // -------- Encode: this tile's 64 rows x 16 d-groups from SMEM --------
    float w0 = enc_w[0], w1 = enc_w[1], w2 = enc_w[2], w3 = enc_w[3];
    {
        float mx = fmaxf(fmaxf(w0, w1), fmaxf(w2, w3));
        float e0 = expf(w0 - mx), e1 = expf(w1 - mx);
        float e2 = expf(w2 - mx), e3 = expf(w3 - mx);
        float inv = 1.0f / (e0 + e1 + e2 + e3);
        w0 = e0 * inv; w1 = e1 * inv; w2 = e2 * inv; w3 = e3 * inv;
    }
    const float tstep = 6.28318530717958647692f / 15.0f;

    const int dl = tid & 15;              // 16 threads per row, consecutive d
    const int rgrp = tid >> 4;            // 8 row-groups
    const int dg = (bn >> 3) + dl;        // global d
    const float freq = freq_bands[dg];

#pragma unroll
    for (int pass = 0; pass < 8; pass++) {
        const int row = pass * 8 + rgrp;         // local row 0..63
        const int mrow = bm + row;
        const int b = mrow >> 8;
        const int s = mrow & 255;

        const float4 pr0 = *(const float4*)&rates[row * RP + dl * 8];
        const float4 pr1 = *(const float4*)&rates[row * RP + dl * 8 + 4];

        const int idx = mrow * Dd + dg;
        const float e = emb[idx];
        const float nz = noise[idx];
        const float sig = 1.0f / (1.0f + expf(-e));
        float rate = sig * 0.9f + 0.05f + nz * 0.1f;
        rate = fminf(fmaxf(rate, 0.0f), 1.0f);
        const int st = (int)(sig * 15.0f);
        const float phase = sig * 6.28318530717958647692f;

        const size_t base = (((size_t)b * Tt) * Ss + s) * Dd + dg;
#pragma unroll 4
        for (int t = 0; t < Tt; t++) {
            const size_t o = base + (size_t)t * (Ss * Dd);
            const float rr = __ldcs(rate_rand + o);
            const float4* pp = (const float4*)(pop_rand + o * Nn);
            const float4 q0 = __ldcs(pp);
            const float4 q1 = __ldcs(pp + 1);
            int cnt = (q0.x < pr0.x) + (q0.y < pr0.y) + (q0.z < pr0.z) + (q0.w < pr0.w)
                    + (q1.x < pr1.x) + (q1.y < pr1.y) + (q1.z < pr1.z) + (q1.w < pr1.w);

            const float wave = my_sinf(fmaf(freq, (float)t * tstep, phase));

            float val = w0 * ((rr < rate) ? 1.0f : 0.0f)
                      + w1 * ((t == st) ? 1.0f : 0.0f)
                      + w2 * ((float)cnt * 0.125f)
                      + w3 * ((wave > 0.5f) ? 1.0f : 0.0f);
            __stcs(out + o, val);
        }
    }
}

// ---------------------------------------------------------------------------
// Launch: conv -> fused (serial; dependency is tile-local, no sync objects)
// ---------------------------------------------------------------------------
extern "C" void kernel_launch(void* const* d_in, const int* in_sizes, int n_in,
                              void* d_out, int out_size) {
    const float* emb       = (const float*)d_in[0];
    const float* popW      = (const float*)d_in[1];
    const float* popb      = (const float*)d_in[2];
    const float* freq      = (const float*)d_in[3];
    const float* encw      = (const float*)d_in[4];
    const float* noise     = (const float*)d_in[5];
    const float* rate_rand = (const float*)d_in[6];
    const float* pop_rand  = (const float*)d_in[7];
    float* out = (float*)d_out;

    cudaFuncSetAttribute(fused_kernel,
                         cudaFuncAttributeMaxDynamicSharedMemorySize, FUSED_SMEM);

    conv_kernel<<<CONV_THREADS / 256, 256>>>(emb, popW);
    fused_kernel<<<dim3(Nc / BN, Mm / BM), 128, FUSED_SMEM>>>(
        popb, emb, noise, freq, encw, rate_rand, pop_rand, out);
}

// round 16
// speedup vs baseline: 1.3233x; 1.3233x over previous
#include <cuda_runtime.h>
#include <cuda_bf16.h>
#include <math.h>
#include <stdint.h>

// Problem shapes (fixed by the dataset)
#define Bb 4
#define Tt 16
#define Ss 256
#define Dd 512
#define Nn 8
#define Mm (Bb * Ss)   // 1024 GEMM rows
#define Kk Dd          // 512  GEMM K
#define Nc (Dd * Nn)   // 4096 GEMM cols

// ---------------------------------------------------------------------------
// Device scratch (no dynamic allocation allowed)
// ---------------------------------------------------------------------------
__device__ __align__(16) float         g_pop_rates[(size_t)Mm * Nc]; // 16.7 MB
__device__ __align__(16) __nv_bfloat16 g_Ehi[(size_t)Mm * Kk];       // [m][k]
__device__ __align__(16) __nv_bfloat16 g_Elo[(size_t)Mm * Kk];
__device__ __align__(16) __nv_bfloat16 g_Whi[(size_t)Kk * Nc];       // [k][n]
__device__ __align__(16) __nv_bfloat16 g_Wlo[(size_t)Kk * Nc];

// ---------------------------------------------------------------------------
// Conversion: fp32 -> bf16 hi/lo split. 8 elems per thread, 16B stores.
// Outputs stored with DEFAULT policy so they stay L2-resident for the GEMM.
// ---------------------------------------------------------------------------
#define E_F4 ((Mm * Kk) / 4)      // 131072
#define W_F4 ((Kk * Nc) / 4)      // 524288
#define CONV_THREADS ((E_F4 + W_F4) / 2)

__device__ __forceinline__ uint32_t pack_hi2(float a, float b) {
    uint32_t ha = (uint32_t)__bfloat16_as_ushort(__float2bfloat16(a));
    uint32_t hb = (uint32_t)__bfloat16_as_ushort(__float2bfloat16(b));
    return ha | (hb << 16);
}
__device__ __forceinline__ uint32_t pack_lo2(float a, float b) {
    float fa = __bfloat162float(__float2bfloat16(a));
    float fb = __bfloat162float(__float2bfloat16(b));
    uint32_t la = (uint32_t)__bfloat16_as_ushort(__float2bfloat16(a - fa));
    uint32_t lb = (uint32_t)__bfloat16_as_ushort(__float2bfloat16(b - fb));
    return la | (lb << 16);
}
__device__ __forceinline__ void conv8(float4 v0, float4 v1,
                                      uint4* __restrict__ dhi,
                                      uint4* __restrict__ dlo) {
    uint4 h, l;
    h.x = pack_hi2(v0.x, v0.y); h.y = pack_hi2(v0.z, v0.w);
    h.z = pack_hi2(v1.x, v1.y); h.w = pack_hi2(v1.z, v1.w);
    l.x = pack_lo2(v0.x, v0.y); l.y = pack_lo2(v0.z, v0.w);
    l.z = pack_lo2(v1.x, v1.y); l.w = pack_lo2(v1.z, v1.w);
    *dhi = h;   // default policy: keep split operands L2-resident
    *dlo = l;
}

__global__ __launch_bounds__(256) void conv_kernel(const float* __restrict__ E,
                                                   const float* __restrict__ W) {
    const int t = blockIdx.x * 256 + threadIdx.x;
    const int i = t * 2;
    if (i < E_F4) {
        // emb is re-read by encode: plain (cached) loads
        float4 v0 = ((const float4*)E)[i];
        float4 v1 = ((const float4*)E)[i + 1];
        conv8(v0, v1, (uint4*)g_Ehi + t, (uint4*)g_Elo + t);
    } else {
        const int j = i - E_F4;
        const int tj = t - E_F4 / 2;
        // W is single-use: streaming loads
        float4 v0 = __ldcs((const float4*)W + j);
        float4 v1 = __ldcs((const float4*)W + j + 1);
        conv8(v0, v1, (uint4*)g_Whi + tj, (uint4*)g_Wlo + tj);
    }
}

// ---------------------------------------------------------------------------
// mma.sync bf16 GEMM (3-term Markidis split) + bias + sigmoid epilogue.
// CTA tile 128x128, BK=32, 8 warps (warp tile 32x64), 3-stage cp.async,
// 2 CTAs/SM. (R12-proven config — at the legacy-HMMA ceiling.)
// ---------------------------------------------------------------------------
#define BM 128
#define BN 128
#define BK 32
#define NK (Kk / BK)          // 16 iterations
#define STAGES 3

#define A_PITCH 40            // bf16 elems per A smem row (32 + 8 pad) -> 80 B
#define B_PITCH 136           // bf16 elems per B smem row (128 + 8 pad) -> 272 B
#define A_BYTES (BM * A_PITCH * 2)   // 10240
#define B_BYTES (BK * B_PITCH * 2)   // 8704
#define ST_AH 0
#define ST_AL A_BYTES
#define ST_BH (2 * A_BYTES)
#define ST_BL (2 * A_BYTES + B_BYTES)
#define STAGE_BYTES (2 * A_BYTES + 2 * B_BYTES)   // 37888
#define GEMM_SMEM (STAGES * STAGE_BYTES)          // 113664

__device__ __forceinline__ uint32_t smem_u32(const void* p) {
    uint32_t a;
    asm("{ .reg .u64 t; cvta.to.shared.u64 t, %1; cvt.u32.u64 %0, t; }"
        : "=r"(a) : "l"(p));
    return a;
}
__device__ __forceinline__ void cp16(uint32_t dst, const void* src) {
    asm volatile("cp.async.cg.shared.global [%0], [%1], 16;"
                 :: "r"(dst), "l"(src) : "memory");
}
__device__ __forceinline__ void ldsm_x4(uint32_t* r, uint32_t addr) {
    asm volatile("ldmatrix.sync.aligned.m8n8.x4.shared.b16 {%0,%1,%2,%3}, [%4];"
                 : "=r"(r[0]), "=r"(r[1]), "=r"(r[2]), "=r"(r[3]) : "r"(addr));
}
__device__ __forceinline__ void ldsm_x4t(uint32_t* r, uint32_t addr) {
    asm volatile("ldmatrix.sync.aligned.m8n8.x4.trans.shared.b16 {%0,%1,%2,%3}, [%4];"
                 : "=r"(r[0]), "=r"(r[1]), "=r"(r[2]), "=r"(r[3]) : "r"(addr));
}
__device__ __forceinline__ void mma16816(float* d, const uint32_t* a, const uint32_t* b) {
    asm volatile(
        "mma.sync.aligned.m16n8k16.row.col.f32.bf16.bf16.f32 "
        "{%0,%1,%2,%3}, {%4,%5,%6,%7}, {%8,%9}, {%0,%1,%2,%3};"
        : "+f"(d[0]), "+f"(d[1]), "+f"(d[2]), "+f"(d[3])
        : "r"(a[0]), "r"(a[1]), "r"(a[2]), "r"(a[3]), "r"(b[0]), "r"(b[1]));
}

__global__ __launch_bounds__(256, 2) void gemm_mma_kernel(const float* __restrict__ bias) {
    extern __shared__ char smem[];
    const uint32_t sbase = smem_u32(smem);
    const int tid = threadIdx.x;
    const int wid = tid >> 5;
    const int ln = tid & 31;
    const int warp_m = wid & 3;       // 4 warps along M (32 rows each)
    const int warp_n = wid >> 2;      // 2 warps along N (64 cols each)
    const int bm = blockIdx.y * BM;
    const int bn = blockIdx.x * BN;

    const int a_row0 = tid >> 2, a_seg = tid & 3;
    const int a_row1 = a_row0 + 64;
    const int b_row0 = tid >> 4, b_seg = tid & 15;
    const int b_row1 = b_row0 + 16;

    auto load_stage = [&](int it) {
        const int k0 = it * BK;
        const uint32_t st = sbase + (it % STAGES) * STAGE_BYTES;
        {
            const size_t g0 = (size_t)(bm + a_row0) * Kk + k0 + a_seg * 8;
            const size_t g1 = (size_t)(bm + a_row1) * Kk + k0 + a_seg * 8;
            const uint32_t s0 = st + ST_AH + a_row0 * (A_PITCH * 2) + a_seg * 16;
            const uint32_t s1 = st + ST_AH + a_row1 * (A_PITCH * 2) + a_seg * 16;
            cp16(s0, g_Ehi + g0);
            cp16(s1, g_Ehi + g1);
            cp16(s0 + (ST_AL - ST_AH), g_Elo + g0);
            cp16(s1 + (ST_AL - ST_AH), g_Elo + g1);
        }
        {
            const size_t g0 = (size_t)(k0 + b_row0) * Nc + bn + b_seg * 8;
            const size_t g1 = (size_t)(k0 + b_row1) * Nc + bn + b_seg * 8;
            const uint32_t s0 = st + ST_BH + b_row0 * (B_PITCH * 2) + b_seg * 16;
            const uint32_t s1 = st + ST_BH + b_row1 * (B_PITCH * 2) + b_seg * 16;
            cp16(s0, g_Whi + g0);
            cp16(s1, g_Whi + g1);
            cp16(s0 + (ST_BL - ST_BH), g_Wlo + g0);
            cp16(s1 + (ST_BL - ST_BH), g_Wlo + g1);
        }
        asm volatile("cp.async.commit_group;" ::: "memory");
    };

    float acc[2][8][4];
#pragma unroll
    for (int i = 0; i < 2; i++)
#pragma unroll
        for (int n = 0; n < 8; n++)
#pragma unroll
            for (int c = 0; c < 4; c++) acc[i][n][c] = 0.0f;

    const int lm_row = ln & 15;
    const int lm_half = ln >> 4;

    load_stage(0);
    load_stage(1);

    for (int it = 0; it < NK; it++) {
        __syncthreads();
        if (it + 2 < NK) load_stage(it + 2);
        if (it < NK - 2)      { asm volatile("cp.async.wait_group 2;" ::: "memory"); }
        else if (it == NK - 2){ asm volatile("cp.async.wait_group 1;" ::: "memory"); }
        else                  { asm volatile("cp.async.wait_group 0;" ::: "memory"); }
        __syncthreads();

        const uint32_t st = sbase + (it % STAGES) * STAGE_BYTES;
        const uint32_t a_hi = st + ST_AH, a_lo = st + ST_AL;
        const uint32_t b_hi = st + ST_BH, b_lo = st + ST_BL;

#pragma unroll
        for (int j = 0; j < 2; j++) {
            uint32_t ah[2][4], al[2][4], bh[8][2], bl[8][2];
#pragma unroll
            for (int i = 0; i < 2; i++) {
                const uint32_t off =
                    (uint32_t)(warp_m * 32 + i * 16 + lm_row) * (A_PITCH * 2)
                    + (uint32_t)(j * 16 + lm_half * 8) * 2;
                ldsm_x4(ah[i], a_hi + off);
                ldsm_x4(al[i], a_lo + off);
            }
#pragma unroll
            for (int p4 = 0; p4 < 4; p4++) {
                const uint32_t off =
                    (uint32_t)(j * 16 + lm_row) * (B_PITCH * 2)
                    + (uint32_t)(warp_n * 64 + p4 * 16 + lm_half * 8) * 2;
                uint32_t r[4];
                ldsm_x4t(r, b_hi + off);
                bh[2 * p4][0] = r[0]; bh[2 * p4][1] = r[1];
                bh[2 * p4 + 1][0] = r[2]; bh[2 * p4 + 1][1] = r[3];
                ldsm_x4t(r, b_lo + off);
                bl[2 * p4][0] = r[0]; bl[2 * p4][1] = r[1];
                bl[2 * p4 + 1][0] = r[2]; bl[2 * p4 + 1][1] = r[3];
            }
#pragma unroll
            for (int i = 0; i < 2; i++)
#pragma unroll
                for (int n = 0; n < 8; n++) {
                    mma16816(acc[i][n], ah[i], bh[n]);
                    mma16816(acc[i][n], ah[i], bl[n]);
                    mma16816(acc[i][n], al[i], bh[n]);
                }
        }
    }

    // Epilogue: bias + sigmoid -> g_pop_rates (default policy: L2-resident)
    const int er = ln >> 2;
    const int ec = (ln & 3) * 2;
#pragma unroll
    for (int i = 0; i < 2; i++) {
        const int row0 = bm + warp_m * 32 + i * 16 + er;
#pragma unroll
        for (int n = 0; n < 8; n++) {
            const int col = bn + warp_n * 64 + n * 8 + ec;
            const float b0 = __ldg(bias + col);
            const float b1 = __ldg(bias + col + 1);
            float2 v0, v1;
            v0.x = 1.0f / (1.0f + expf(-(acc[i][n][0] + b0)));
            v0.y = 1.0f / (1.0f + expf(-(acc[i][n][1] + b1)));
            v1.x = 1.0f / (1.0f + expf(-(acc[i][n][2] + b0)));
            v1.y = 1.0f / (1.0f + expf(-(acc[i][n][3] + b1)));
            *(float2*)(g_pop_rates + (size_t)row0 * Nc + col) = v0;
            *(float2*)(g_pop_rates + (size_t)(row0 + 8) * Nc + col) = v1;
        }
    }
}

// ---------------------------------------------------------------------------
// Accurate fp32 sin (Cody-Waite + degree-9 minimax); fast-math immune.
// ---------------------------------------------------------------------------
__device__ __forceinline__ float my_sinf(float x) {
    const float INV_PI = 0.318309886183790672f;
    const float PI_HI = 3.14159274101257324f;
    const float PI_LO = -8.74227765734758577e-08f;
    float kf = rintf(x * INV_PI);
    float r = fmaf(-kf, PI_HI, x);
    r = fmaf(-kf, PI_LO, r);
    float s = r * r;
    float p = fmaf(s, 2.6083159809786593e-06f, -1.9810690719168633e-04f);
    p = fmaf(s, p, 8.3330785855650902e-03f);
    p = fmaf(s, p, -1.6666659712791443e-01f);
    float res = fmaf(r * s, p, r);
    int k = (int)kf;
    return (k & 1) ? -res : res;
}

// ---------------------------------------------------------------------------
// Fused encoder: TWO adjacent d-cells per thread (d even pairs).
// Per t: 8B rate_rand + 64B pop_rand loads, 8B out store — all contiguous.
// Doubles per-thread bytes-in-flight vs the 1-cell version.
// ---------------------------------------------------------------------------
__global__ __launch_bounds__(256) void encode_kernel(
    const float* __restrict__ emb,
    const float* __restrict__ noise,
    const float* __restrict__ freq_bands,
    const float* __restrict__ enc_w,
    const float* __restrict__ rate_rand,
    const float* __restrict__ pop_rand,
    float* __restrict__ out)
{
    const int pidx = blockIdx.x * 256 + threadIdx.x;  // pair index 0..262143
    const int idx = pidx << 1;                        // even cell index
    const int d = idx & (Dd - 1);                     // even d
    const int s = (idx >> 9) & (Ss - 1);
    const int b = idx >> 17;

    float w0 = enc_w[0], w1 = enc_w[1], w2 = enc_w[2], w3 = enc_w[3];
    {
        float mx = fmaxf(fmaxf(w0, w1), fmaxf(w2, w3));
        float e0 = expf(w0 - mx), e1 = expf(w1 - mx);
        float e2 = expf(w2 - mx), e3 = expf(w3 - mx);
        float inv = 1.0f / (e0 + e1 + e2 + e3);
        w0 = e0 * inv; w1 = e1 * inv; w2 = e2 * inv; w3 = e3 * inv;
    }

    const float2 e2v = *(const float2*)(emb + idx);
    const float2 nz2 = *(const float2*)(noise + idx);
    const float2 fb2 = *(const float2*)(freq_bands + d);

    const float sig0 = 1.0f / (1.0f + expf(-e2v.x));
    const float sig1 = 1.0f / (1.0f + expf(-e2v.y));
    float rate0 = fminf(fmaxf(sig0 * 0.9f + 0.05f + nz2.x * 0.1f, 0.0f), 1.0f);
    float rate1 = fminf(fmaxf(sig1 * 0.9f + 0.05f + nz2.y * 0.1f, 0.0f), 1.0f);
    const int st0 = (int)(sig0 * 15.0f);
    const int st1 = (int)(sig1 * 15.0f);
    const float ph0 = sig0 * 6.28318530717958647692f;
    const float ph1 = sig1 * 6.28318530717958647692f;

    const float4* prp = (const float4*)(g_pop_rates + (size_t)idx * Nn);
    const float4 pA0 = prp[0];
    const float4 pA1 = prp[1];
    const float4 pB0 = prp[2];
    const float4 pB1 = prp[3];

    const float tstep = 6.28318530717958647692f / 15.0f;
    const size_t base = (((size_t)b * Tt) * Ss + s) * Dd + d;
#pragma unroll 4
    for (int t = 0; t < Tt; t++) {
        const size_t o = base + (size_t)t * (Ss * Dd);
        const float2 rr = __ldcs((const float2*)(rate_rand + o));
        const float4* pp = (const float4*)(pop_rand + o * Nn);
        const float4 q0 = __ldcs(pp);
        const float4 q1 = __ldcs(pp + 1);
        const float4 q2 = __ldcs(pp + 2);
        const float4 q3 = __ldcs(pp + 3);
        int cnt0 = (q0.x < pA0.x) + (q0.y < pA0.y) + (q0.z < pA0.z) + (q0.w < pA0.w)
                 + (q1.x < pA1.x) + (q1.y < pA1.y) + (q1.z < pA1.z) + (q1.w < pA1.w);
        int cnt1 = (q2.x < pB0.x) + (q2.y < pB0.y) + (q2.z < pB0.z) + (q2.w < pB0.w)
                 + (q3.x < pB1.x) + (q3.y < pB1.y) + (q3.z < pB1.z) + (q3.w < pB1.w);

        const float tval = (float)t * tstep;
        const float wave0 = my_sinf(fmaf(fb2.x, tval, ph0));
        const float wave1 = my_sinf(fmaf(fb2.y, tval, ph1));

        float2 val;
        val.x = w0 * ((rr.x < rate0) ? 1.0f : 0.0f)
              + w1 * ((t == st0) ? 1.0f : 0.0f)
              + w2 * ((float)cnt0 * 0.125f)
              + w3 * ((wave0 > 0.5f) ? 1.0f : 0.0f);
        val.y = w0 * ((rr.y < rate1) ? 1.0f : 0.0f)
              + w1 * ((t == st1) ? 1.0f : 0.0f)
              + w2 * ((float)cnt1 * 0.125f)
              + w3 * ((wave1 > 0.5f) ? 1.0f : 0.0f);
        __stcs((float2*)(out + o), val);
    }
}

// ---------------------------------------------------------------------------
// Launch (serial, single stream — overlap schemes conclusively regressed)
// ---------------------------------------------------------------------------
extern "C" void kernel_launch(void* const* d_in, const int* in_sizes, int n_in,
                              void* d_out, int out_size) {
    const float* emb       = (const float*)d_in[0];
    const float* popW      = (const float*)d_in[1];
    const float* popb      = (const float*)d_in[2];
    const float* freq      = (const float*)d_in[3];
    const float* encw      = (const float*)d_in[4];
    const float* noise     = (const float*)d_in[5];
    const float* rate_rand = (const float*)d_in[6];
    const float* pop_rand  = (const float*)d_in[7];
    float* out = (float*)d_out;

    cudaFuncSetAttribute(gemm_mma_kernel,
                         cudaFuncAttributeMaxDynamicSharedMemorySize, GEMM_SMEM);

    conv_kernel<<<CONV_THREADS / 256, 256>>>(emb, popW);
    gemm_mma_kernel<<<dim3(Nc / BN, Mm / BM), 256, GEMM_SMEM>>>(popb);
    encode_kernel<<<(Mm * Dd / 2) / 256, 256>>>(emb, noise, freq, encw,
                                                rate_rand, pop_rand, out);
}

// round 17
// speedup vs baseline: 1.3292x; 1.0045x over previous
#include <cuda_runtime.h>
#include <cuda_bf16.h>
#include <math.h>
#include <stdint.h>

// Problem shapes (fixed by the dataset)
#define Bb 4
#define Tt 16
#define Ss 256
#define Dd 512
#define Nn 8
#define Mm (Bb * Ss)   // 1024 GEMM rows
#define Kk Dd          // 512  GEMM K
#define Nc (Dd * Nn)   // 4096 GEMM cols

// ---------------------------------------------------------------------------
// Device scratch (no dynamic allocation allowed)
// ---------------------------------------------------------------------------
__device__ __align__(16) float         g_pop_rates[(size_t)Mm * Nc]; // 16.7 MB
__device__ __align__(16) __nv_bfloat16 g_Ehi[(size_t)Mm * Kk];       // [m][k]
__device__ __align__(16) __nv_bfloat16 g_Elo[(size_t)Mm * Kk];
__device__ __align__(16) __nv_bfloat16 g_Whi[(size_t)Nc * Kk];       // [n][k] (transposed!)
__device__ __align__(16) __nv_bfloat16 g_Wlo[(size_t)Nc * Kk];

// ---------------------------------------------------------------------------
// Conversion: E split (linear) + W split WITH transpose to [n][k].
// ---------------------------------------------------------------------------
#define E_F4 ((Mm * Kk) / 4)      // 131072
#define E_BLOCKS 256              // 256 blocks x 256 thr x 2 float4
#define W_TBLOCKS (128 * 16)      // 32x32 tiles over [512][4096]

__device__ __forceinline__ uint32_t pack_hi2(float a, float b) {
    uint32_t ha = (uint32_t)__bfloat16_as_ushort(__float2bfloat16(a));
    uint32_t hb = (uint32_t)__bfloat16_as_ushort(__float2bfloat16(b));
    return ha | (hb << 16);
}
__device__ __forceinline__ uint32_t pack_lo2(float a, float b) {
    float fa = __bfloat162float(__float2bfloat16(a));
    float fb = __bfloat162float(__float2bfloat16(b));
    uint32_t la = (uint32_t)__bfloat16_as_ushort(__float2bfloat16(a - fa));
    uint32_t lb = (uint32_t)__bfloat16_as_ushort(__float2bfloat16(b - fb));
    return la | (lb << 16);
}

__global__ __launch_bounds__(256) void conv_kernel(const float* __restrict__ E,
                                                   const float* __restrict__ W) {
    if (blockIdx.x < E_BLOCKS) {
        // ---- E split: 2 float4 per thread, packed 16B stores ----
        const int t = blockIdx.x * 256 + threadIdx.x;
        const int i = t * 2;
        const float4 v0 = ((const float4*)E)[i];
        const float4 v1 = ((const float4*)E)[i + 1];
        uint4 h, l;
        h.x = pack_hi2(v0.x, v0.y); h.y = pack_hi2(v0.z, v0.w);
        h.z = pack_hi2(v1.x, v1.y); h.w = pack_hi2(v1.z, v1.w);
        l.x = pack_lo2(v0.x, v0.y); l.y = pack_lo2(v0.z, v0.w);
        l.z = pack_lo2(v1.x, v1.y); l.w = pack_lo2(v1.z, v1.w);
        ((uint4*)g_Ehi)[t] = h;
        ((uint4*)g_Elo)[t] = l;
    } else {
        // ---- W split + transpose: W[k][n] -> g_W{hi,lo}[n][k] ----
        __shared__ float tile[32][33];
        const int bid = blockIdx.x - E_BLOCKS;
        const int n0 = (bid & 127) * 32;
        const int k0 = (bid >> 7) * 32;
        const int tx = threadIdx.x & 31;
        const int ty = threadIdx.x >> 5;      // 0..7
#pragma unroll
        for (int r = 0; r < 32; r += 8)
            tile[ty + r][tx] = __ldcs(W + (size_t)(k0 + ty + r) * Nc + n0 + tx);
        __syncthreads();
#pragma unroll
        for (int r = 0; r < 32; r += 8) {
            const float v = tile[tx][ty + r];  // = W[k0+tx][n0+ty+r]
            const __nv_bfloat16 hi = __float2bfloat16(v);
            const __nv_bfloat16 lo =
                __float2bfloat16(v - __bfloat162float(hi));
            const size_t o = (size_t)(n0 + ty + r) * Kk + k0 + tx;
            g_Whi[o] = hi;
            g_Wlo[o] = lo;
        }
    }
}

// ---------------------------------------------------------------------------
// mma.sync bf16 GEMM (3-term Markidis split) + bias + sigmoid epilogue.
// CTA tile 128x128, BK=32, 8 warps (warp tile 32x64), 3-stage cp.async,
// 2 CTAs/SM. B now [n][k]: non-trans ldsm, XOR-swizzled 64B rows.
// ---------------------------------------------------------------------------
#define BM 128
#define BN 128
#define BK 32
#define NK (Kk / BK)          // 16 iterations
#define STAGES 3

#define A_PITCH 40            // bf16 elems per A smem row (32 + 8 pad) -> 80 B
#define A_BYTES (BM * A_PITCH * 2)   // 10240
#define B_BYTES (BN * 64)            // 8192  (128 n-rows x 64B, swizzled)
#define ST_AH 0
#define ST_AL A_BYTES
#define ST_BH (2 * A_BYTES)
#define ST_BL (2 * A_BYTES + B_BYTES)
#define STAGE_BYTES (2 * A_BYTES + 2 * B_BYTES)   // 36864
#define GEMM_SMEM (STAGES * STAGE_BYTES)          // 110592

// B swizzle: chunk c (16B units within a 64B row) at row n -> c ^ ((n>>1)&3)
#define BSW(n, c) ((uint32_t)(n) * 64u + (uint32_t)(((c) ^ (((n) >> 1) & 3)) * 16))

__device__ __forceinline__ uint32_t smem_u32(const void* p) {
    uint32_t a;
    asm("{ .reg .u64 t; cvta.to.shared.u64 t, %1; cvt.u32.u64 %0, t; }"
        : "=r"(a) : "l"(p));
    return a;
}
__device__ __forceinline__ void cp16(uint32_t dst, const void* src) {
    asm volatile("cp.async.cg.shared.global [%0], [%1], 16;"
                 :: "r"(dst), "l"(src) : "memory");
}
__device__ __forceinline__ void ldsm_x4(uint32_t* r, uint32_t addr) {
    asm volatile("ldmatrix.sync.aligned.m8n8.x4.shared.b16 {%0,%1,%2,%3}, [%4];"
                 : "=r"(r[0]), "=r"(r[1]), "=r"(r[2]), "=r"(r[3]) : "r"(addr));
}
__device__ __forceinline__ void mma16816(float* d, const uint32_t* a, const uint32_t* b) {
    asm volatile(
        "mma.sync.aligned.m16n8k16.row.col.f32.bf16.bf16.f32 "
        "{%0,%1,%2,%3}, {%4,%5,%6,%7}, {%8,%9}, {%0,%1,%2,%3};"
        : "+f"(d[0]), "+f"(d[1]), "+f"(d[2]), "+f"(d[3])
        : "r"(a[0]), "r"(a[1]), "r"(a[2]), "r"(a[3]), "r"(b[0]), "r"(b[1]));
}

__global__ __launch_bounds__(256, 2) void gemm_mma_kernel(const float* __restrict__ bias) {
    extern __shared__ char smem[];
    const uint32_t sbase = smem_u32(smem);
    const int tid = threadIdx.x;
    const int wid = tid >> 5;
    const int ln = tid & 31;
    const int warp_m = wid & 3;       // 4 warps along M (32 rows each)
    const int warp_n = wid >> 2;      // 2 warps along N (64 cols each)
    const int bm = blockIdx.y * BM;
    const int bn = blockIdx.x * BN;

    // A loader: 512 chunks/array -> 2 rows per thread
    const int a_row0 = tid >> 2, a_seg = tid & 3;
    const int a_row1 = a_row0 + 64;
    // B loader: 512 chunks/array -> rows tid>>2 and +64, chunk c = tid&3
    const int b_n0 = tid >> 2, b_c = tid & 3;
    const int b_n1 = b_n0 + 64;

    auto load_stage = [&](int it) {
        const int k0 = it * BK;
        const uint32_t st = sbase + (it % STAGES) * STAGE_BYTES;
        {
            const size_t g0 = (size_t)(bm + a_row0) * Kk + k0 + a_seg * 8;
            const size_t g1 = (size_t)(bm + a_row1) * Kk + k0 + a_seg * 8;
            const uint32_t s0 = st + ST_AH + a_row0 * (A_PITCH * 2) + a_seg * 16;
            const uint32_t s1 = st + ST_AH + a_row1 * (A_PITCH * 2) + a_seg * 16;
            cp16(s0, g_Ehi + g0);
            cp16(s1, g_Ehi + g1);
            cp16(s0 + (ST_AL - ST_AH), g_Elo + g0);
            cp16(s1 + (ST_AL - ST_AH), g_Elo + g1);
        }
        {
            const size_t g0 = (size_t)(bn + b_n0) * Kk + k0 + b_c * 8;
            const size_t g1 = (size_t)(bn + b_n1) * Kk + k0 + b_c * 8;
            const uint32_t s0 = st + ST_BH + BSW(b_n0, b_c);
            const uint32_t s1 = st + ST_BH + BSW(b_n1, b_c);
            cp16(s0, g_Whi + g0);
            cp16(s1, g_Whi + g1);
            cp16(s0 + (ST_BL - ST_BH), g_Wlo + g0);
            cp16(s1 + (ST_BL - ST_BH), g_Wlo + g1);
        }
        asm volatile("cp.async.commit_group;" ::: "memory");
    };

    float acc[2][8][4];
#pragma unroll
    for (int i = 0; i < 2; i++)
#pragma unroll
        for (int n = 0; n < 8; n++)
#pragma unroll
            for (int c = 0; c < 4; c++) acc[i][n][c] = 0.0f;

    const int lm_row = ln & 15;
    const int lm_half = ln >> 4;
    // B non-trans ldsm group mapping
    const int grp = ln >> 3;              // 0..3
    const int grow = ln & 7;
    const int nb_t = (grp >= 2) ? 8 : 0;  // n offset within n16 block
    const int kc_t = grp & 1;             // k half (8-bf16 units)

    load_stage(0);
    load_stage(1);

    for (int it = 0; it < NK; it++) {
        __syncthreads();
        if (it + 2 < NK) load_stage(it + 2);
        if (it < NK - 2)      { asm volatile("cp.async.wait_group 2;" ::: "memory"); }
        else if (it == NK - 2){ asm volatile("cp.async.wait_group 1;" ::: "memory"); }
        else                  { asm volatile("cp.async.wait_group 0;" ::: "memory"); }
        __syncthreads();

        const uint32_t st = sbase + (it % STAGES) * STAGE_BYTES;
        const uint32_t a_hi = st + ST_AH, a_lo = st + ST_AL;
        const uint32_t b_hi = st + ST_BH, b_lo = st + ST_BL;

#pragma unroll
        for (int j = 0; j < 2; j++) {          // k16 sub-steps within BK=32
            uint32_t ah[2][4], al[2][4], bh[8][2], bl[8][2];
#pragma unroll
            for (int i = 0; i < 2; i++) {
                const uint32_t off =
                    (uint32_t)(warp_m * 32 + i * 16 + lm_row) * (A_PITCH * 2)
                    + (uint32_t)(j * 16 + lm_half * 8) * 2;
                ldsm_x4(ah[i], a_hi + off);
                ldsm_x4(al[i], a_lo + off);
            }
#pragma unroll
            for (int p4 = 0; p4 < 4; p4++) {
                const int n_local = warp_n * 64 + p4 * 16 + grow + nb_t;
                const int c = 2 * j + kc_t;
                const uint32_t off = BSW(n_local, c);
                uint32_t r[4];
                ldsm_x4(r, b_hi + off);
                bh[2 * p4][0] = r[0]; bh[2 * p4][1] = r[1];
                bh[2 * p4 + 1][0] = r[2]; bh[2 * p4 + 1][1] = r[3];
                ldsm_x4(r, b_lo + off);
                bl[2 * p4][0] = r[0]; bl[2 * p4][1] = r[1];
                bl[2 * p4 + 1][0] = r[2]; bl[2 * p4 + 1][1] = r[3];
            }
#pragma unroll
            for (int i = 0; i < 2; i++)
#pragma unroll
                for (int n = 0; n < 8; n++) {
                    mma16816(acc[i][n], ah[i], bh[n]);
                    mma16816(acc[i][n], ah[i], bl[n]);
                    mma16816(acc[i][n], al[i], bh[n]);
                }
        }
    }

    // Epilogue: bias + sigmoid -> g_pop_rates
    const int er = ln >> 2;
    const int ec = (ln & 3) * 2;
#pragma unroll
    for (int i = 0; i < 2; i++) {
        const int row0 = bm + warp_m * 32 + i * 16 + er;
#pragma unroll
        for (int n = 0; n < 8; n++) {
            const int col = bn + warp_n * 64 + n * 8 + ec;
            const float b0 = __ldg(bias + col);
            const float b1 = __ldg(bias + col + 1);
            float2 v0, v1;
            v0.x = 1.0f / (1.0f + expf(-(acc[i][n][0] + b0)));
            v0.y = 1.0f / (1.0f + expf(-(acc[i][n][1] + b1)));
            v1.x = 1.0f / (1.0f + expf(-(acc[i][n][2] + b0)));
            v1.y = 1.0f / (1.0f + expf(-(acc[i][n][3] + b1)));
            *(float2*)(g_pop_rates + (size_t)row0 * Nc + col) = v0;
            *(float2*)(g_pop_rates + (size_t)(row0 + 8) * Nc + col) = v1;
        }
    }
}

// ---------------------------------------------------------------------------
// Accurate fp32 sin (Cody-Waite + degree-9 minimax); fast-math immune.
// ---------------------------------------------------------------------------
__device__ __forceinline__ float my_sinf(float x) {
    const float INV_PI = 0.318309886183790672f;
    const float PI_HI = 3.14159274101257324f;
    const float PI_LO = -8.74227765734758577e-08f;
    float kf = rintf(x * INV_PI);
    float r = fmaf(-kf, PI_HI, x);
    r = fmaf(-kf, PI_LO, r);
    float s = r * r;
    float p = fmaf(s, 2.6083159809786593e-06f, -1.9810690719168633e-04f);
    p = fmaf(s, p, 8.3330785855650902e-03f);
    p = fmaf(s, p, -1.6666659712791443e-01f);
    float res = fmaf(r * s, p, r);
    int k = (int)kf;
    return (k & 1) ? -res : res;
}

// ---------------------------------------------------------------------------
// Fused encoder: two adjacent d-cells per thread (d even pairs).
// ---------------------------------------------------------------------------
__global__ __launch_bounds__(256) void encode_kernel(
    const float* __restrict__ emb,
    const float* __restrict__ noise,
    const float* __restrict__ freq_bands,
    const float* __restrict__ enc_w,
    const float* __restrict__ rate_rand,
    const float* __restrict__ pop_rand,
    float* __restrict__ out)
{
    const int pidx = blockIdx.x * 256 + threadIdx.x;
    const int idx = pidx << 1;
    const int d = idx & (Dd - 1);
    const int s = (idx >> 9) & (Ss - 1);
    const int b = idx >> 17;

    float w0 = enc_w[0], w1 = enc_w[1], w2 = enc_w[2], w3 = enc_w[3];
    {
        float mx = fmaxf(fmaxf(w0, w1), fmaxf(w2, w3));
        float e0 = expf(w0 - mx), e1 = expf(w1 - mx);
        float e2 = expf(w2 - mx), e3 = expf(w3 - mx);
        float inv = 1.0f / (e0 + e1 + e2 + e3);
        w0 = e0 * inv; w1 = e1 * inv; w2 = e2 * inv; w3 = e3 * inv;
    }

    const float2 e2v = *(const float2*)(emb + idx);
    const float2 nz2 = *(const float2*)(noise + idx);
    const float2 fb2 = *(const float2*)(freq_bands + d);

    const float sig0 = 1.0f / (1.0f + expf(-e2v.x));
    const float sig1 = 1.0f / (1.0f + expf(-e2v.y));
    float rate0 = fminf(fmaxf(sig0 * 0.9f + 0.05f + nz2.x * 0.1f, 0.0f), 1.0f);
    float rate1 = fminf(fmaxf(sig1 * 0.9f + 0.05f + nz2.y * 0.1f, 0.0f), 1.0f);
    const int st0 = (int)(sig0 * 15.0f);
    const int st1 = (int)(sig1 * 15.0f);
    const float ph0 = sig0 * 6.28318530717958647692f;
    const float ph1 = sig1 * 6.28318530717958647692f;

    const float4* prp = (const float4*)(g_pop_rates + (size_t)idx * Nn);
    const float4 pA0 = prp[0];
    const float4 pA1 = prp[1];
    const float4 pB0 = prp[2];
    const float4 pB1 = prp[3];

    const float tstep = 6.28318530717958647692f / 15.0f;
    const size_t base = (((size_t)b * Tt) * Ss + s) * Dd + d;
#pragma unroll 4
    for (int t = 0; t < Tt; t++) {
        const size_t o = base + (size_t)t * (Ss * Dd);
        const float2 rr = __ldcs((const float2*)(rate_rand + o));
        const float4* pp = (const float4*)(pop_rand + o * Nn);
        const float4 q0 = __ldcs(pp);
        const float4 q1 = __ldcs(pp + 1);
        const float4 q2 = __ldcs(pp + 2);
        const float4 q3 = __ldcs(pp + 3);
        int cnt0 = (q0.x < pA0.x) + (q0.y < pA0.y) + (q0.z < pA0.z) + (q0.w < pA0.w)
                 + (q1.x < pA1.x) + (q1.y < pA1.y) + (q1.z < pA1.z) + (q1.w < pA1.w);
        int cnt1 = (q2.x < pB0.x) + (q2.y < pB0.y) + (q2.z < pB0.z) + (q2.w < pB0.w)
                 + (q3.x < pB1.x) + (q3.y < pB1.y) + (q3.z < pB1.z) + (q3.w < pB1.w);

        const float tval = (float)t * tstep;
        const float wave0 = my_sinf(fmaf(fb2.x, tval, ph0));
        const float wave1 = my_sinf(fmaf(fb2.y, tval, ph1));

        float2 val;
        val.x = w0 * ((rr.x < rate0) ? 1.0f : 0.0f)
              + w1 * ((t == st0) ? 1.0f : 0.0f)
              + w2 * ((float)cnt0 * 0.125f)
              + w3 * ((wave0 > 0.5f) ? 1.0f : 0.0f);
        val.y = w0 * ((rr.y < rate1) ? 1.0f : 0.0f)
              + w1 * ((t == st1) ? 1.0f : 0.0f)
              + w2 * ((float)cnt1 * 0.125f)
              + w3 * ((wave1 > 0.5f) ? 1.0f : 0.0f);
        __stcs((float2*)(out + o), val);
    }
}

// ---------------------------------------------------------------------------
// Launch (serial, single stream)
// ---------------------------------------------------------------------------
extern "C" void kernel_launch(void* const* d_in, const int* in_sizes, int n_in,
                              void* d_out, int out_size) {
    const float* emb       = (const float*)d_in[0];
    const float* popW      = (const float*)d_in[1];
    const float* popb      = (const float*)d_in[2];
    const float* freq      = (const float*)d_in[3];
    const float* encw      = (const float*)d_in[4];
    const float* noise     = (const float*)d_in[5];
    const float* rate_rand = (const float*)d_in[6];
    const float* pop_rand  = (const float*)d_in[7];
    float* out = (float*)d_out;

    cudaFuncSetAttribute(gemm_mma_kernel,
                         cudaFuncAttributeMaxDynamicSharedMemorySize, GEMM_SMEM);

    conv_kernel<<<E_BLOCKS + W_TBLOCKS, 256>>>(emb, popW);
    gemm_mma_kernel<<<dim3(Nc / BN, Mm / BM), 256, GEMM_SMEM>>>(popb);
    encode_kernel<<<(Mm * Dd / 2) / 256, 256>>>(emb, noise, freq, encw,
                                                rate_rand, pop_rand, out);
}